// round 1
// baseline (speedup 1.0000x reference)
#include <cuda_runtime.h>
#include <math.h>

#define BB 16
#define CC 64
#define NN 1024
#define NH 4
#define FF 15
#define FH 60
#define KK 9
#define ALPHA 0.2f

// ---------------- scratch (device globals; no allocation) ----------------
__device__ __align__(16) float g_h[BB*CC*NN];      // [b][c][n]
__device__ __align__(16) float g_sq[BB*NN];
__device__ __align__(16) float g_dist[(size_t)BB*NN*NN];   // 64MB
__device__ __align__(16) int   g_idx[BB*NN*KK];
__device__ __align__(16) float g_Wh[BB*NN*FH];     // [b][n][60] (head-major 4x15)
__device__ __align__(16) float g_f1[BB*NN*NH];
__device__ __align__(16) float g_f2[BB*NN*NH];
__device__ __align__(16) float g_den[BB*NN*NH];
__device__ __align__(16) float g_hcat[BB*NN*FH];
__device__ __align__(16) float g_Who[BB*NN*CC];    // [b][n][64]
__device__ __align__(16) float g_f1o[BB*NN];
__device__ __align__(16) float g_f2o[BB*NN];
__device__ __align__(16) float g_deno[BB*NN];

// ---------------- K1: L2 normalize over C ----------------
__global__ void k_norm(const float* __restrict__ x) {
    int t = blockIdx.x * 256 + threadIdx.x;          // [0, B*N)
    int b = t >> 10, n = t & 1023;
    const float* xp = x + (size_t)b * CC * NN + n;
    float s = 0.f;
#pragma unroll
    for (int c = 0; c < CC; c++) { float v = xp[c * NN]; s += v * v; }
    float nrm = fmaxf(sqrtf(s), 1e-12f);
    float r = 1.0f / nrm;
    float s2 = 0.f;
    float* hp = g_h + (size_t)b * CC * NN + n;
#pragma unroll
    for (int c = 0; c < CC; c++) {
        float v = xp[c * NN] * r;
        hp[c * NN] = v;
        s2 += v * v;
    }
    g_sq[t] = s2;
}

// ---------------- K2: gram / dist matrix (fp32, f32x2-packed FFMA) ----------------
extern __shared__ float smem_g[];
__global__ __launch_bounds__(256) void k_gram() {
    float* As = smem_g;                // [64][128]
    float* Bs = smem_g + 64 * 128;     // [64][128]
    int b = blockIdx.z;
    int i0 = blockIdx.y * 128, j0 = blockIdx.x * 128;
    int t = threadIdx.x;
    const float* hb = g_h + (size_t)b * CC * NN;
#pragma unroll
    for (int r = 0; r < 8; r++) {
        int lin = t + r * 256;               // float4 index into [64][32]
        int c = lin >> 5, pos = lin & 31;
        *(float4*)(As + c * 128 + pos * 4) = *(const float4*)(hb + c * NN + i0 + pos * 4);
        *(float4*)(Bs + c * 128 + pos * 4) = *(const float4*)(hb + c * NN + j0 + pos * 4);
    }
    __syncthreads();
    int tx = t & 15, ty = t >> 4;
    const float* ap = As + ty * 8;
    const float* bp = Bs + tx * 8;
    unsigned long long acc[8][4];
#pragma unroll
    for (int ii = 0; ii < 8; ii++)
#pragma unroll
        for (int jj = 0; jj < 4; jj++) acc[ii][jj] = 0ull;

#pragma unroll 8
    for (int c = 0; c < 64; c++) {
        float4 a0 = *(const float4*)(ap + c * 128);
        float4 a1 = *(const float4*)(ap + c * 128 + 4);
        ulonglong2 b0 = *(const ulonglong2*)(bp + c * 128);
        ulonglong2 b1 = *(const ulonglong2*)(bp + c * 128 + 4);
        unsigned long long bb[4] = { b0.x, b0.y, b1.x, b1.y };
        float av[8] = { a0.x, a0.y, a0.z, a0.w, a1.x, a1.y, a1.z, a1.w };
#pragma unroll
        for (int ii = 0; ii < 8; ii++) {
            unsigned long long pa;
            asm("mov.b64 %0, {%1, %1};" : "=l"(pa) : "f"(av[ii]));
#pragma unroll
            for (int jj = 0; jj < 4; jj++)
                asm("fma.rn.f32x2 %0, %1, %2, %0;" : "+l"(acc[ii][jj]) : "l"(pa), "l"(bb[jj]));
        }
    }
    const float* sqb = g_sq + b * NN;
    float sj[8];
#pragma unroll
    for (int jj = 0; jj < 8; jj++) sj[jj] = sqb[j0 + tx * 8 + jj];
#pragma unroll
    for (int ii = 0; ii < 8; ii++) {
        int i = i0 + ty * 8 + ii;
        float si = sqb[i];
        float o[8];
#pragma unroll
        for (int jj = 0; jj < 4; jj++) {
            unsigned long long v = acc[ii][jj];
            float lo = __uint_as_float((unsigned)(v & 0xffffffffull));
            float hi = __uint_as_float((unsigned)(v >> 32));
            o[2 * jj]     = fmaf(-2.f, lo, si) + sj[2 * jj];
            o[2 * jj + 1] = fmaf(-2.f, hi, si) + sj[2 * jj + 1];
        }
        float* dst = g_dist + ((size_t)(b * NN + i)) * NN + j0 + tx * 8;
        *(float4*)dst       = make_float4(o[0], o[1], o[2], o[3]);
        *(float4*)(dst + 4) = make_float4(o[4], o[5], o[6], o[7]);
    }
}

// ---------------- K_top9: warp per row, u64 keys, exact tie-break ----------------
__global__ void k_top9() {
    int warp = threadIdx.x >> 5, lane = threadIdx.x & 31;
    int row = blockIdx.x * 8 + warp;            // [0, B*N)
    const float* dr = g_dist + (size_t)row * NN;
    unsigned long long best[9];
#pragma unroll
    for (int q = 0; q < 9; q++) best[q] = 0xFFFFFFFFFFFFFFFFull;
    for (int j = lane; j < NN; j += 32) {
        float d = dr[j];
        unsigned u = __float_as_uint(d);
        u = (u & 0x80000000u) ? ~u : (u | 0x80000000u);   // order-preserving map
        unsigned long long key = ((unsigned long long)u << 32) | (unsigned)j;
        if (key < best[8]) {
            best[8] = key;
#pragma unroll
            for (int q = 8; q > 0; q--) {
                unsigned long long a = best[q - 1], c = best[q];
                best[q - 1] = (a < c) ? a : c;
                best[q]     = (a < c) ? c : a;
            }
        }
    }
    int p = 0;
    for (int r = 0; r < 9; r++) {
        unsigned long long v = best[p];
        unsigned long long m = v;
#pragma unroll
        for (int off = 16; off; off >>= 1) {
            unsigned long long o = __shfl_xor_sync(0xFFFFFFFFu, m, off);
            m = (o < m) ? o : m;
        }
        if (v == m) p++;                         // keys unique (contain j)
        if (lane == 0) g_idx[row * 9 + r] = (int)(m & 0xFFFFFFFFull);
    }
}

// ---------------- K3: Wh (4 heads), f1/f2, zero den ----------------
__global__ void k3(const float* __restrict__ Wheads, const float* __restrict__ aheads) {
    __shared__ float Wc[CC * FH];
    __shared__ float as[NH * 2 * FF];
    int t = threadIdx.x;
    int b = blockIdx.x >> 2;
    int n0 = (blockIdx.x & 3) * 256;
    for (int idx = t; idx < NH * CC * FF; idx += 256) {
        int h = idx / (CC * FF); int rem = idx % (CC * FF);
        int c = rem / FF; int f = rem % FF;
        Wc[c * FH + h * FF + f] = Wheads[idx];
    }
    if (t < NH * 2 * FF) as[t] = aheads[t];
    __syncthreads();
    int n = n0 + t;
    const float* hp = g_h + (size_t)b * CC * NN + n;
    float acc[FH];
#pragma unroll
    for (int f = 0; f < FH; f++) acc[f] = 0.f;
    for (int c = 0; c < CC; c++) {
        float hc = hp[c * NN];
#pragma unroll
        for (int f = 0; f < FH; f++) acc[f] = fmaf(hc, Wc[c * FH + f], acc[f]);
    }
    size_t row = (size_t)b * NN + n;
    float4* wout = (float4*)(g_Wh + row * FH);
#pragma unroll
    for (int q = 0; q < FH / 4; q++)
        wout[q] = make_float4(acc[4 * q], acc[4 * q + 1], acc[4 * q + 2], acc[4 * q + 3]);
#pragma unroll
    for (int h = 0; h < NH; h++) {
        float f1 = 0.f, f2 = 0.f;
#pragma unroll
        for (int f = 0; f < FF; f++) {
            f1 = fmaf(acc[h * FF + f], as[h * 2 * FF + f], f1);
            f2 = fmaf(acc[h * FF + f], as[h * 2 * FF + FF + f], f2);
        }
        g_f1[row * NH + h] = f1;
        g_f2[row * NH + h] = f2;
        g_den[row * NH + h] = 0.f;
    }
}

// ---------------- K4: column denominators (heads), scatter atomics ----------------
__global__ void k4() {
    int row = blockIdx.x * 256 + threadIdx.x;     // b*N + i
    int bbase = row & ~1023;
    float4 f1v = *(const float4*)(g_f1 + (size_t)row * 4);
    const int* ip = g_idx + row * 9;
#pragma unroll
    for (int k = 0; k < KK; k++) {
        int jr = bbase + ip[k];
        float4 f2v = *(const float4*)(g_f2 + (size_t)jr * 4);
        float* dp = g_den + (size_t)jr * 4;
        float e0 = f1v.x + f2v.x; e0 = e0 > 0.f ? e0 : ALPHA * e0;
        float e1 = f1v.y + f2v.y; e1 = e1 > 0.f ? e1 : ALPHA * e1;
        float e2 = f1v.z + f2v.z; e2 = e2 > 0.f ? e2 : ALPHA * e2;
        float e3 = f1v.w + f2v.w; e3 = e3 > 0.f ? e3 : ALPHA * e3;
        atomicAdd(dp + 0, expf(e0));
        atomicAdd(dp + 1, expf(e1));
        atomicAdd(dp + 2, expf(e2));
        atomicAdd(dp + 3, expf(e3));
    }
}

// ---------------- K5: head aggregation + ELU -> hcat ----------------
__global__ void k5() {
    int t = threadIdx.x;                 // 240 = 4 nodes x 60
    int local = t / FH, c = t % FH;
    int row = blockIdx.x * 4 + local;    // b*N + i
    int bbase = row & ~1023;
    int h = c / FF;
    const int* ip = g_idx + row * 9;
    float f1v = g_f1[(size_t)row * 4 + h];
    float acc = 0.f;
#pragma unroll
    for (int k = 0; k < KK; k++) {
        int jr = bbase + ip[k];
        float e = f1v + g_f2[(size_t)jr * 4 + h];
        e = e > 0.f ? e : ALPHA * e;
        float w = expf(e) / g_den[(size_t)jr * 4 + h];
        acc = fmaf(w, g_Wh[(size_t)jr * FH + c], acc);
    }
    g_hcat[(size_t)row * FH + c] = acc > 0.f ? acc : expm1f(acc);
}

// ---------------- K6: W_out GEMM + f1o/f2o, zero deno ----------------
__global__ void k6(const float* __restrict__ Wout, const float* __restrict__ aout) {
    __shared__ float Wo[FH * CC];
    __shared__ float av[2 * CC];
    int t = threadIdx.x;
    int b = blockIdx.x >> 2;
    int n0 = (blockIdx.x & 3) * 256;
    for (int idx = t; idx < FH * CC; idx += 256) Wo[idx] = Wout[idx];
    if (t < 2 * CC) av[t] = aout[t];
    __syncthreads();
    int n = n0 + t;
    size_t row = (size_t)b * NN + n;
    const float* hr = g_hcat + row * FH;
    float acc[CC];
#pragma unroll
    for (int o = 0; o < CC; o++) acc[o] = 0.f;
#pragma unroll
    for (int c4 = 0; c4 < FH / 4; c4++) {
        float4 hv = *(const float4*)(hr + c4 * 4);
        float hs[4] = { hv.x, hv.y, hv.z, hv.w };
#pragma unroll
        for (int q = 0; q < 4; q++) {
            int c = c4 * 4 + q;
#pragma unroll
            for (int o = 0; o < CC; o++) acc[o] = fmaf(hs[q], Wo[c * CC + o], acc[o]);
        }
    }
    float4* wout4 = (float4*)(g_Who + row * CC);
#pragma unroll
    for (int q = 0; q < CC / 4; q++)
        wout4[q] = make_float4(acc[4 * q], acc[4 * q + 1], acc[4 * q + 2], acc[4 * q + 3]);
    float f1 = 0.f, f2 = 0.f;
#pragma unroll
    for (int o = 0; o < CC; o++) {
        f1 = fmaf(acc[o], av[o], f1);
        f2 = fmaf(acc[o], av[CC + o], f2);
    }
    g_f1o[row] = f1;
    g_f2o[row] = f2;
    g_deno[row] = 0.f;
}

// ---------------- K7: output-layer denominators ----------------
__global__ void k7() {
    int row = blockIdx.x * 256 + threadIdx.x;
    int bbase = row & ~1023;
    float f1 = g_f1o[row];
    const int* ip = g_idx + row * 9;
#pragma unroll
    for (int k = 0; k < KK; k++) {
        int jr = bbase + ip[k];
        float e = f1 + g_f2o[jr];
        e = e > 0.f ? e : ALPHA * e;
        atomicAdd(g_deno + jr, expf(e));
    }
}

// ---------------- K8: out-aggregate + ELU + LReLU + conv1x1 + BN + residual ----------------
__global__ void k8(const float* __restrict__ x, const float* __restrict__ cw,
                   const float* __restrict__ cb, const float* __restrict__ gamma,
                   const float* __restrict__ beta, float* __restrict__ out) {
    __shared__ float cws[CC * 65];
    __shared__ float ys[32 * 65];
    __shared__ float ws[32 * KK];
    __shared__ int   js[32 * KK];
    int t = threadIdx.x;
    int b = blockIdx.x >> 5;
    int n0 = (blockIdx.x & 31) * 32;
    for (int idx = t; idx < CC * CC; idx += 256) {
        int o = idx >> 6, c = idx & 63;
        cws[o * 65 + c] = cw[idx];
    }
    for (int idx = t; idx < 32 * KK; idx += 256) {
        int node = idx / KK, k = idx % KK;
        int row = b * NN + n0 + node;
        int jr = b * NN + g_idx[row * 9 + k];
        float e = g_f1o[row] + g_f2o[jr];
        e = e > 0.f ? e : ALPHA * e;
        ws[idx] = expf(e) / g_deno[jr];
        js[idx] = jr;
    }
    __syncthreads();
#pragma unroll
    for (int p = 0; p < 8; p++) {
        int idx = t + p * 256;
        int node = idx >> 6, c = idx & 63;
        float acc = 0.f;
#pragma unroll
        for (int k = 0; k < KK; k++)
            acc = fmaf(ws[node * KK + k], g_Who[(size_t)js[node * KK + k] * CC + c], acc);
        float e = acc > 0.f ? acc : expm1f(acc);   // ELU
        ys[node * 65 + c] = e > 0.f ? e : 0.01f * e; // LeakyReLU(0.01)
    }
    __syncthreads();
    int node = t & 31, og = t >> 5;
    float bnr = 1.0f / sqrtf(1.0f + 1e-5f);
#pragma unroll
    for (int p = 0; p < 8; p++) {
        int o = og * 8 + p;
        float s = cb[o];
        const float* yr = ys + node * 65;
        const float* cr = cws + o * 65;
#pragma unroll
        for (int c = 0; c < CC; c++) s = fmaf(cr[c], yr[c], s);
        s = s * bnr * gamma[o] + beta[o];
        size_t oidx = ((size_t)(b * CC + o)) * NN + n0 + node;
        out[oidx] = s + x[oidx];
    }
}

// ---------------- launch ----------------
extern "C" void kernel_launch(void* const* d_in, const int* in_sizes, int n_in,
                              void* d_out, int out_size) {
    const float* x      = (const float*)d_in[0];
    const float* Wheads = (const float*)d_in[1];
    const float* aheads = (const float*)d_in[2];
    const float* Wout   = (const float*)d_in[3];
    const float* aout   = (const float*)d_in[4];
    const float* convw  = (const float*)d_in[5];
    const float* convb  = (const float*)d_in[6];
    const float* gamma  = (const float*)d_in[7];
    const float* beta   = (const float*)d_in[8];
    float* out = (float*)d_out;

    static bool attr_set = false;
    if (!attr_set) {
        cudaFuncSetAttribute(k_gram, cudaFuncAttributeMaxDynamicSharedMemorySize, 65536);
        attr_set = true;
    }

    k_norm<<<BB * NN / 256, 256>>>(x);
    k_gram<<<dim3(8, 8, BB), 256, 65536>>>();
    k_top9<<<BB * NN / 8, 256>>>();
    k3<<<BB * 4, 256>>>(Wheads, aheads);
    k4<<<BB * NN / 256, 256>>>();
    k5<<<BB * NN / 4, 240>>>();
    k6<<<BB * 4, 256>>>(Wout, aout);
    k7<<<BB * NN / 256, 256>>>();
    k8<<<BB * 32, 256>>>(x, convw, convb, gamma, beta, out);
}